// round 1
// baseline (speedup 1.0000x reference)
#include <cuda_runtime.h>
#include <cuda_bf16.h>
#include <math_constants.h>

#define NN 50000
#define NE 800000
#define DIM 256
#define NINNER 768          // 3 * 256 (q|k|v concatenated)
#define CAP 128             // max in-degree capacity (Poisson(16) -> P(>128) ~ 0)

// ---------------- scratch (static device globals; no allocation) ----------------
__device__ float g_W[DIM * NINNER];        // packed [K=256][N=768] weights
__device__ float g_bias[NINNER];
__device__ float g_Y[(size_t)NN * NINNER]; // qkv projections, row layout [q(256)|k(256)|v(256)]
__device__ int   g_cnt[NN];
__device__ int   g_adj[(size_t)NN * CAP];  // src node ids of incoming edges per dst

// ---------------- packed f32x2 FMA helper (Blackwell FFMA2) ----------------
__device__ __forceinline__ float2 fma2(float2 a, float2 b, float2 c) {
    unsigned long long au = *reinterpret_cast<unsigned long long*>(&a);
    unsigned long long bu = *reinterpret_cast<unsigned long long*>(&b);
    unsigned long long cu = *reinterpret_cast<unsigned long long*>(&c);
    unsigned long long du;
    asm("fma.rn.f32x2 %0, %1, %2, %3;" : "=l"(du) : "l"(au), "l"(bu), "l"(cu));
    return *reinterpret_cast<float2*>(&du);
}

// ---------------- kernel 1: pack weights + bias ----------------
__global__ void pack_w_kernel(const float* __restrict__ Wq, const float* __restrict__ bq,
                              const float* __restrict__ Wk, const float* __restrict__ bk,
                              const float* __restrict__ Wv, const float* __restrict__ bv) {
    int i = blockIdx.x * blockDim.x + threadIdx.x;
    if (i < DIM * NINNER) {
        int k = i / NINNER;
        int c = i % NINNER;
        float w;
        if (c < 256)       w = Wq[k * 256 + c];
        else if (c < 512)  w = Wk[k * 256 + (c - 256)];
        else               w = Wv[k * 256 + (c - 512)];
        g_W[(size_t)k * NINNER + c] = w;
    }
    if (i < NINNER) {
        float b;
        if (i < 256)       b = bq[i];
        else if (i < 512)  b = bk[i - 256];
        else               b = bv[i - 512];
        g_bias[i] = b;
    }
}

// ---------------- kernel 2: fused QKV GEMM  Y = X @ W + bias ----------------
// M=50000, N=768, K=256. BM=128, BN=64, BK=16, 256 threads, 8x4 micro-tile
// computed as 4x4 float2 pairs through fma.rn.f32x2.
#define BM 128
#define BN 64
#define BK 16

__global__ __launch_bounds__(256) void gemm_kernel(const float* __restrict__ X) {
    __shared__ float As[2][BK][BM];
    __shared__ float Bs[2][BK][BN];

    const int bn = blockIdx.x * BN;
    const int bm = blockIdx.y * BM;
    const int t = threadIdx.x;
    const int trow = t >> 4;   // 0..15
    const int tcol = t & 15;   // 0..15

    float2 acc[4][4];
#pragma unroll
    for (int i = 0; i < 4; i++)
#pragma unroll
        for (int j = 0; j < 4; j++) acc[i][j] = make_float2(0.f, 0.f);

    // ---- stage loaders ----
    // A tile: 128 rows x 16 k = 512 float4; each thread loads 2.
    // B tile: 16 k x 64 n = 256 float4; each thread loads 1.
    auto load_tiles = [&](int buf, int kc) {
#pragma unroll
        for (int u = 0; u < 2; u++) {
            int idx = t + u * 256;
            int r = idx >> 2;          // 0..127 row in tile
            int kq = idx & 3;          // which float4 in k-chunk
            int row = bm + r;
            float4 val = make_float4(0.f, 0.f, 0.f, 0.f);
            if (row < NN)
                val = *reinterpret_cast<const float4*>(X + (size_t)row * DIM + kc + kq * 4);
            As[buf][kq * 4 + 0][r] = val.x;
            As[buf][kq * 4 + 1][r] = val.y;
            As[buf][kq * 4 + 2][r] = val.z;
            As[buf][kq * 4 + 3][r] = val.w;
        }
        {
            int kr = t >> 4;           // 0..15
            int nq = t & 15;           // 0..15
            float4 v = *reinterpret_cast<const float4*>(g_W + (size_t)(kc + kr) * NINNER + bn + nq * 4);
            *reinterpret_cast<float4*>(&Bs[buf][kr][nq * 4]) = v;
        }
    };

    load_tiles(0, 0);
    __syncthreads();

#pragma unroll 4
    for (int kc = 0; kc < DIM; kc += BK) {
        int buf = (kc / BK) & 1;
        if (kc + BK < DIM) load_tiles(buf ^ 1, kc + BK);

#pragma unroll
        for (int kk = 0; kk < BK; kk++) {
            float2 a[4];
            float b[4];
#pragma unroll
            for (int i = 0; i < 4; i++)
                a[i] = *reinterpret_cast<float2*>(&As[buf][kk][trow * 8 + 2 * i]);
#pragma unroll
            for (int j = 0; j < 4; j++)
                b[j] = Bs[buf][kk][tcol * 4 + j];
#pragma unroll
            for (int i = 0; i < 4; i++)
#pragma unroll
                for (int j = 0; j < 4; j++)
                    acc[i][j] = fma2(a[i], make_float2(b[j], b[j]), acc[i][j]);
        }
        __syncthreads();
    }

    // epilogue: add bias, store
#pragma unroll
    for (int i = 0; i < 4; i++) {
        int row0 = bm + trow * 8 + 2 * i;
#pragma unroll
        for (int j = 0; j < 4; j++) {
            int n = bn + tcol * 4 + j;
            float bia = g_bias[n];
            if (row0 < NN)     g_Y[(size_t)row0 * NINNER + n]       = acc[i][j].x + bia;
            if (row0 + 1 < NN) g_Y[(size_t)(row0 + 1) * NINNER + n] = acc[i][j].y + bia;
        }
    }
}

// ---------------- kernel 3: zero in-degree counters ----------------
__global__ void zero_cnt_kernel() {
    int i = blockIdx.x * blockDim.x + threadIdx.x;
    if (i < NN) g_cnt[i] = 0;
}

// ---------------- kernel 4: scatter edges into per-dst adjacency ----------------
__global__ void scatter_kernel(const int* __restrict__ src, const int* __restrict__ dst) {
    int e = blockIdx.x * blockDim.x + threadIdx.x;
    if (e < NE) {
        int d = dst[e];
        int p = atomicAdd(&g_cnt[d], 1);
        if (p < CAP) g_adj[(size_t)d * CAP + p] = src[e];
    }
}

// ---------------- kernel 5: per-dst online-softmax attention ----------------
// One block per dst node, one warp per head (8 warps x 32 lanes = 256 threads).
__global__ __launch_bounds__(256) void attn_kernel(float* __restrict__ out) {
    const int d = blockIdx.x;
    const int h = threadIdx.x >> 5;
    const int lane = threadIdx.x & 31;

    int cnt = g_cnt[d];
    if (cnt > CAP) cnt = CAP;
    const int* adj = &g_adj[(size_t)d * CAP];

    const float kd = g_Y[(size_t)d * NINNER + 256 + h * 32 + lane];

    float m = -CUDART_INF_F;
    float z = 0.f;
    float acc = 0.f;
    const float scale = 0.17677669529663687f;  // 1/sqrt(32)

    for (int i = 0; i < cnt; i++) {
        int s = adj[i];  // uniform across warp
        const float* row = g_Y + (size_t)s * NINNER + h * 32 + lane;
        float qd = row[0];
        float dot = qd * kd;
#pragma unroll
        for (int off = 16; off > 0; off >>= 1)
            dot += __shfl_xor_sync(0xFFFFFFFFu, dot, off);
        float score = dot * scale;

        float mn = fmaxf(m, score);
        float corr = __expf(m - mn);     // 0 on first edge (m = -inf)
        float w = __expf(score - mn);
        float vd = row[512];             // v component
        z = z * corr + w;
        acc = acc * corr + w * vd;
        m = mn;
    }

    float r = (cnt > 0) ? acc / z : 0.f;
    out[(size_t)d * 256 + h * 32 + lane] = r;
}

// ---------------- launch ----------------
extern "C" void kernel_launch(void* const* d_in, const int* in_sizes, int n_in,
                              void* d_out, int out_size) {
    const float* x  = (const float*)d_in[0];
    const float* Wq = (const float*)d_in[1];
    const float* bq = (const float*)d_in[2];
    const float* Wk = (const float*)d_in[3];
    const float* bk = (const float*)d_in[4];
    const float* Wv = (const float*)d_in[5];
    const float* bv = (const float*)d_in[6];
    const int* src  = (const int*)d_in[7];
    const int* dst  = (const int*)d_in[8];
    float* out = (float*)d_out;

    pack_w_kernel<<<(DIM * NINNER + 255) / 256, 256>>>(Wq, bq, Wk, bk, Wv, bv);

    dim3 ggrid(NINNER / BN, (NN + BM - 1) / BM);  // 12 x 391
    gemm_kernel<<<ggrid, 256>>>(x);

    zero_cnt_kernel<<<(NN + 255) / 256, 256>>>();
    scatter_kernel<<<(NE + 255) / 256, 256>>>(src, dst);

    attn_kernel<<<NN, 256>>>(out);
}